// round 16
// baseline (speedup 1.0000x reference)
#include <cuda_runtime.h>
#include <cuda_fp16.h>
#include <cstdint>

#define BB 4
#define NN 8192
#define MM 2048
#define KK 8
#define F1C 256
#define F2C 256
#define C0 259
#define H2 256
#define C2IN 512
#define NTILES 2048

// ---------------- scratch (__device__ globals) ----------------
__device__ float g_y0[(size_t)BB * MM * 128];                      // s0 * (W0_feat @ feature2)
__device__ __half g_midh[(size_t)BB * H2 * NN];                    // mlp1 output (fp16)
__device__ int   g_idx[BB * NN * KK];
__device__ __align__(16) uint16_t g_w1h[128 * 128];
__device__ __align__(16) uint16_t g_w2h[256 * 128];
__device__ __align__(16) uint16_t g_w20h[256 * 512];

__device__ __forceinline__ uint16_t f2h(float x) {
    return __half_as_ushort(__float2half_rn(x));
}
__device__ __forceinline__ uint32_t smem_u32(const void* p) {
    uint32_t a;
    asm("{ .reg .u64 t; cvta.to.shared.u64 t, %1; cvt.u32.u64 %0, t; }" : "=r"(a) : "l"(p));
    return a;
}
__device__ __forceinline__ uint32_t packh2(float lo, float hi) {
    return (uint32_t)f2h(lo) | ((uint32_t)f2h(hi) << 16);
}

// ---------------- mma.sync / ldmatrix / cp.async primitives ----------------
__device__ __forceinline__ void ldsm4(uint32_t r[4], uint32_t addr) {
    asm volatile("ldmatrix.sync.aligned.m8n8.x4.shared.b16 {%0,%1,%2,%3}, [%4];"
                 : "=r"(r[0]), "=r"(r[1]), "=r"(r[2]), "=r"(r[3]) : "r"(addr));
}
__device__ __forceinline__ void ldsm4t(uint32_t r[4], uint32_t addr) {
    asm volatile("ldmatrix.sync.aligned.m8n8.x4.trans.shared.b16 {%0,%1,%2,%3}, [%4];"
                 : "=r"(r[0]), "=r"(r[1]), "=r"(r[2]), "=r"(r[3]) : "r"(addr));
}
__device__ __forceinline__ void mma16816(float c[4], const uint32_t a[4], const uint32_t* b) {
    asm volatile("mma.sync.aligned.m16n8k16.row.col.f32.f16.f16.f32 "
                 "{%0,%1,%2,%3}, {%4,%5,%6,%7}, {%8,%9}, {%0,%1,%2,%3};"
                 : "+f"(c[0]), "+f"(c[1]), "+f"(c[2]), "+f"(c[3])
                 : "r"(a[0]), "r"(a[1]), "r"(a[2]), "r"(a[3]), "r"(b[0]), "r"(b[1]));
}
#define CP16(dst, src) asm volatile("cp.async.cg.shared.global [%0], [%1], 16;" :: "r"(dst), "l"(src))
#define CP_COMMIT()    asm volatile("cp.async.commit_group;")
#define CP_WAIT(n)     asm volatile("cp.async.wait_group %0;" :: "n"(n))

#define LD1 136
#define LDW 72

__device__ __forceinline__ void zero_c(float c[2][8][4]) {
#pragma unroll
    for (int mi = 0; mi < 2; mi++)
#pragma unroll
        for (int nt = 0; nt < 8; nt++)
#pragma unroll
            for (int q = 0; q < 4; q++) c[mi][nt][q] = 0.0f;
}

// K=128 GEMM (W stride LD1): rows [mw*32,+32) x cols [nw*64,+64)
__device__ __forceinline__ void gemm_ms(uint32_t xu, uint32_t wu, int mw, int nw,
                                        int lid, float c[2][8][4]) {
    uint32_t aA0 = wu + (uint32_t)(((mw * 32 + (lid & 15)) * LD1 + (lid >> 4) * 8) * 2);
    uint32_t aA1 = aA0 + 16 * LD1 * 2;
    uint32_t aB  = xu + (uint32_t)(((lid & 15) * LD1 + nw * 64 + (lid >> 4) * 8) * 2);
#pragma unroll
    for (int kt = 0; kt < 8; kt++) {
        uint32_t A0[4], A1[4];
        ldsm4(A0, aA0 + kt * 32);
        ldsm4(A1, aA1 + kt * 32);
#pragma unroll
        for (int ng = 0; ng < 4; ng++) {
            uint32_t Bv[4];
            ldsm4t(Bv, aB + kt * 16 * LD1 * 2 + ng * 32);
            mma16816(c[0][2 * ng],     A0, Bv);
            mma16816(c[0][2 * ng + 1], A0, Bv + 2);
            mma16816(c[1][2 * ng],     A1, Bv);
            mma16816(c[1][2 * ng + 1], A1, Bv + 2);
        }
    }
}

// K=64 GEMM (W stride LDW=72)
__device__ __forceinline__ void gemm_k64(uint32_t xu, uint32_t wu, int mw, int nw,
                                         int lid, float c[2][8][4]) {
    uint32_t aA0 = wu + (uint32_t)(((mw * 32 + (lid & 15)) * LDW + (lid >> 4) * 8) * 2);
    uint32_t aA1 = aA0 + 16 * LDW * 2;
    uint32_t aB  = xu + (uint32_t)(((lid & 15) * LD1 + nw * 64 + (lid >> 4) * 8) * 2);
#pragma unroll
    for (int kt = 0; kt < 4; kt++) {
        uint32_t A0[4], A1[4];
        ldsm4(A0, aA0 + kt * 32);
        ldsm4(A1, aA1 + kt * 32);
#pragma unroll
        for (int ng = 0; ng < 4; ng++) {
            uint32_t Bv[4];
            ldsm4t(Bv, aB + kt * 16 * LD1 * 2 + ng * 32);
            mma16816(c[0][2 * ng],     A0, Bv);
            mma16816(c[0][2 * ng + 1], A0, Bv + 2);
            mma16816(c[1][2 * ng],     A1, Bv);
            mma16816(c[1][2 * ng + 1], A1, Bv + 2);
        }
    }
}

// cp.async a 128x128 fp16 matrix (row stride srcstride bytes) into LD1-padded smem
__device__ __forceinline__ void cpa_mat(uint32_t dst, const char* src, size_t srcstride, int t) {
#pragma unroll
    for (int k = 0; k < 8; k++) {
        int i = t + k * 256, row = i >> 4, q = i & 15;
        CP16(dst + (uint32_t)(((row * 17) + q) * 16), src + (size_t)row * srcstride + q * 16);
    }
}

// ---------------------------------------------------------------------------
// pre_kernel: ONE launch.
//   blocks [0, 1024): KNN, 8-way chunked per query (32 queries/block)
//   blocks [1024, 1280): y0
//   blocks [1280, 1984): weight conversion
// ---------------------------------------------------------------------------
#define PRE_KNN_BLKS 1024
#define PRE_Y0_BLKS 256
#define PRE_W_BLKS 704
#define PRE_BLKS (PRE_KNN_BLKS + PRE_Y0_BLKS + PRE_W_BLKS)
#define PRE_SMEM 33792
#define MCHK 256

__global__ __launch_bounds__(256) void pre_kernel(
    const float* __restrict__ pos1, const float* __restrict__ pos2,
    const float* __restrict__ f2,
    const float* __restrict__ W0, const float* __restrict__ S0,
    const float* __restrict__ W1, const float* __restrict__ S1,
    const float* __restrict__ W2, const float* __restrict__ S2,
    const float* __restrict__ W20, const float* __restrict__ S20) {
    extern __shared__ __align__(16) char psm[];
    const int bid = blockIdx.x, t = threadIdx.x;

    if (bid < PRE_KNN_BLKS) {
        // ============ KNN: 32 queries x 8 chunks of 256 points ============
        float* sXY = (float*)psm;                 // MM*2 floats (16 KB)
        float* sZW = (float*)psm + MM * 2;        // MM*2 floats (16 KB)
        const int b = bid >> 8, qbase = (bid & 255) * 32;
        const float* p2 = pos2 + (size_t)b * 3 * MM;
        for (int m = t; m < MM; m += 256) {
            float x = p2[m], y = p2[MM + m], z = p2[2 * MM + m];
            int pp = m >> 1, ln = m & 1;
            sXY[pp * 4 + ln] = x;     sXY[pp * 4 + 2 + ln] = y;
            sZW[pp * 4 + ln] = z;     sZW[pp * 4 + 2 + ln] = x * x + y * y + z * z;
        }
        __syncthreads();

        const int q = t >> 3, ch = t & 7;
        const int n = qbase + q;
        const float* p1 = pos1 + (size_t)b * 3 * NN;
        const float px = p1[n], py = p1[NN + n], pz = p1[2 * NN + n];
        const float n1 = px * px + py * py + pz * pz;
        const float mx2 = -2.0f * px, my2 = -2.0f * py, mz2 = -2.0f * pz;
        uint64_t QX, QY, QZ, NP;
        asm("mov.b64 %0, {%1, %2};" : "=l"(QX) : "f"(mx2), "f"(mx2));
        asm("mov.b64 %0, {%1, %2};" : "=l"(QY) : "f"(my2), "f"(my2));
        asm("mov.b64 %0, {%1, %2};" : "=l"(QZ) : "f"(mz2), "f"(mz2));
        asm("mov.b64 %0, {%1, %2};" : "=l"(NP) : "f"(n1), "f"(n1));

        float bestd[KK]; int besti[KK];
#pragma unroll
        for (int i = 0; i < KK; i++) { bestd[i] = 1e30f; besti[i] = ch * MCHK; }
        float worst = 1e30f; int wslot = 0;

        auto ins = [&](float dv, int iv) {
            if (dv < worst) {
#pragma unroll
                for (int i = 0; i < KK; i++)
                    if (i == wslot) { bestd[i] = dv; besti[i] = iv; }
                worst = bestd[0]; wslot = 0;
#pragma unroll
                for (int i = 1; i < KK; i++)
                    if (bestd[i] > worst) { worst = bestd[i]; wslot = i; }
            }
        };

        uint32_t aXY = smem_u32(sXY) + ch * (MCHK / 2) * 16;
        uint32_t aZW = smem_u32(sZW) + ch * (MCHK / 2) * 16;
        for (int g = 0; g < MCHK / 4; g++) {
            uint64_t X0, Y0, X1, Y1, Z0, W0v, Z1, W1v, t0, t1;
            asm("ld.shared.v2.u64 {%0,%1}, [%2];"    : "=l"(X0), "=l"(Y0) : "r"(aXY));
            asm("ld.shared.v2.u64 {%0,%1}, [%2+16];" : "=l"(X1), "=l"(Y1) : "r"(aXY));
            asm("ld.shared.v2.u64 {%0,%1}, [%2];"    : "=l"(Z0), "=l"(W0v) : "r"(aZW));
            asm("ld.shared.v2.u64 {%0,%1}, [%2+16];" : "=l"(Z1), "=l"(W1v) : "r"(aZW));
            aXY += 32; aZW += 32;
            asm("add.rn.f32x2 %0, %1, %2;"     : "=l"(t0) : "l"(W0v), "l"(NP));
            asm("fma.rn.f32x2 %0, %1, %2, %3;" : "=l"(t0) : "l"(QZ), "l"(Z0), "l"(t0));
            asm("fma.rn.f32x2 %0, %1, %2, %3;" : "=l"(t0) : "l"(QY), "l"(Y0), "l"(t0));
            asm("fma.rn.f32x2 %0, %1, %2, %3;" : "=l"(t0) : "l"(QX), "l"(X0), "l"(t0));
            asm("add.rn.f32x2 %0, %1, %2;"     : "=l"(t1) : "l"(W1v), "l"(NP));
            asm("fma.rn.f32x2 %0, %1, %2, %3;" : "=l"(t1) : "l"(QZ), "l"(Z1), "l"(t1));
            asm("fma.rn.f32x2 %0, %1, %2, %3;" : "=l"(t1) : "l"(QY), "l"(Y1), "l"(t1));
            asm("fma.rn.f32x2 %0, %1, %2, %3;" : "=l"(t1) : "l"(QX), "l"(X1), "l"(t1));
            float d0, d1, d2, d3;
            asm("mov.b64 {%0,%1}, %2;" : "=f"(d0), "=f"(d1) : "l"(t0));
            asm("mov.b64 {%0,%1}, %2;" : "=f"(d2), "=f"(d3) : "l"(t1));
            float mn = fminf(fminf(d0, d1), fminf(d2, d3));
            if (mn < worst) {
                int ib = ch * MCHK + g * 4;
                ins(d0, ib); ins(d1, ib + 1); ins(d2, ib + 2); ins(d3, ib + 3);
            }
        }
        __syncthreads();                          // done reading pos2 smem
        // candidates: cd (float, 8 KB... 2048*4) at psm, ci (int) at psm+16384
        float* cd = (float*)psm;                  // [32*64]
        int*   ci = (int*)(psm + 16384);          // [32*64]
#pragma unroll
        for (int i = 0; i < KK; i++) {
            cd[q * 64 + ch * 8 + i] = bestd[i];
            ci[q * 64 + ch * 8 + i] = besti[i];
        }
        __syncthreads();
        // merge: thread t<32 handles query t: top-8 of 64, (d, idx) lexicographic
        if (t < 32) {
            float md[64]; int mi_[64];
#pragma unroll 8
            for (int j = 0; j < 64; j++) { md[j] = cd[t * 64 + j]; mi_[j] = ci[t * 64 + j]; }
            int* outp = g_idx + ((size_t)b * NN + qbase + t) * KK;
#pragma unroll
            for (int s = 0; s < KK; s++) {
                float dm = 1e38f; int im = 0x7fffffff, jm = 0;
                for (int j = 0; j < 64; j++) {
                    bool bt = (md[j] < dm) || (md[j] == dm && mi_[j] < im);
                    if (bt) { dm = md[j]; im = mi_[j]; jm = j; }
                }
                outp[s] = im;
                md[jm] = 1e38f;
            }
        }

    } else if (bid < PRE_KNN_BLKS + PRE_Y0_BLKS) {
        // ================= y0 =================
        float* tile = (float*)psm;                // [256][33]
        const int yb = bid - PRE_KNN_BLKS;
        const int b = yb >> 6, m0 = (yb & 63) * 32;
        for (int i = t; i < 256 * 32; i += 256) {
            int c = i >> 5, j = i & 31;
            tile[c * 33 + j] = f2[((size_t)b * F2C + c) * MM + m0 + j];
        }
        __syncthreads();
        const int r = t & 127, mh = t >> 7;
        float acc[16];
#pragma unroll
        for (int j = 0; j < 16; j++) acc[j] = 0.0f;
        const float* wrow = W0 + (size_t)r * C0;
#pragma unroll 4
        for (int c = 0; c < 256; c++) {
            float w = __ldg(&wrow[c]);
#pragma unroll
            for (int j = 0; j < 16; j++) acc[j] = fmaf(w, tile[c * 33 + mh * 16 + j], acc[j]);
        }
        float s0 = __ldg(&S0[r]);
        for (int j = 0; j < 16; j++)
            g_y0[((size_t)b * MM + m0 + mh * 16 + j) * 128 + r] = acc[j] * s0;

    } else {
        // ================= weight conversion =================
        int i = (bid - PRE_KNN_BLKS - PRE_Y0_BLKS) * 256 + t;
        if (i < 16384) {
            g_w1h[i] = f2h(W1[i] * __ldg(&S1[i >> 7]));
        } else if (i < 49152) {
            int j = i - 16384;
            g_w2h[j] = f2h(W2[j] * __ldg(&S2[j >> 7]));
        } else if (i < 180224) {
            int j = i - 49152;
            g_w20h[j] = f2h(W20[j] * __ldg(&S20[j >> 9]));
        }
    }
}

// ---------------------------------------------------------------------------
// mlp1 PERSISTENT: all weights resident; tiles of 16 points.
// ---------------------------------------------------------------------------
#define X1OFF 0
#define WS1 34816
#define WS2 69632
#define WS3 104448
#define STGOFF 139264
#define PRMOFF 147456
#define DSMEM1 150528

__global__ __launch_bounds__(256, 1) void mlp1_mma(
    const float* __restrict__ pos1, const float* __restrict__ pos2,
    const float* __restrict__ W0full, const float* __restrict__ S0,
    const float* __restrict__ B0, const float* __restrict__ B1,
    const float* __restrict__ B2) {
    extern __shared__ __align__(32) char smp[];

    const int t = threadIdx.x, wid = t >> 5, lid = t & 31;
    const int mw = wid & 3, nw = wid >> 2;

    const uint32_t xu  = smem_u32(smp + X1OFF);
    const uint32_t wu1 = smem_u32(smp + WS1);
    const uint32_t wu2 = smem_u32(smp + WS2);
    const uint32_t wu3 = smem_u32(smp + WS3);
    uint16_t* stage  = (uint16_t*)(smp + STGOFF);
    int*   sidx   = (int*)(smp + PRMOFF);
    float* sw0pos = (float*)(smp + PRMOFF + 512);
    float* sB0    = (float*)(smp + PRMOFF + 2048);
    float* sB1    = (float*)(smp + PRMOFF + 2560);

    cpa_mat(wu1, (const char*)g_w1h, 256, t);
    cpa_mat(wu2, (const char*)g_w2h, 256, t);
    cpa_mat(wu3, (const char*)(g_w2h + 16384), 256, t);
    CP_COMMIT();

    for (int i = t; i < 384; i += 256) {
        int d = i >> 7, r = i & 127;
        sw0pos[i] = W0full[(size_t)r * C0 + 256 + d] * __ldg(&S0[r]);
    }
    if (t < 128) { sB0[t] = B0[t]; sB1[t] = B1[t]; }

    float c[2][8][4];

    for (int tile = blockIdx.x; tile < NTILES; tile += gridDim.x) {
        const int b = tile >> 9, n0 = (tile & 511) * 16;

        if (t < 128) sidx[t] = g_idx[((size_t)b * NN + n0) * KK + t];
        __syncthreads();

        // epilogue 0: gather y0 + pos correction, +b, ReLU -> X0 [k][n]
        {
            int c2 = t & 63, qh = t >> 6;
            int ca = 2 * c2;
            int ma = sidx[ca], mb2 = sidx[ca + 1];
            int n = n0 + (c2 >> 2);
            float pa0 = pos2[((size_t)b * 3 + 0) * MM + ma]  - pos1[((size_t)b * 3 + 0) * NN + n];
            float pa1 = pos2[((size_t)b * 3 + 1) * MM + ma]  - pos1[((size_t)b * 3 + 1) * NN + n];
            float pa2 = pos2[((size_t)b * 3 + 2) * MM + ma]  - pos1[((size_t)b * 3 + 2) * NN + n];
            float pb0 = pos2[((size_t)b * 3 + 0) * MM + mb2] - pos1[((size_t)b * 3 + 0) * NN + n];
            float pb1 = pos2[((size_t)b * 3 + 1) * MM + mb2] - pos1[((size_t)b * 3 + 1) * NN + n];
            float pb2 = pos2[((size_t)b * 3 + 2) * MM + mb2] - pos1[((size_t)b * 3 + 2) * NN + n];
            const float4* ya = (const float4*)(g_y0 + ((size_t)b * MM + ma)  * 128 + 32 * qh);
            const float4* yb = (const float4*)(g_y0 + ((size_t)b * MM + mb2) * 128 + 32 * qh);
            uint32_t* X32 = (uint32_t*)(smp + X1OFF);
#pragma unroll
            for (int i = 0; i < 8; i++) {
                float4 va = ya[i], vb = yb[i];
                float aa[4] = {va.x, va.y, va.z, va.w};
                float bb[4] = {vb.x, vb.y, vb.z, vb.w};
#pragma unroll
                for (int j = 0; j < 4; j++) {
                    int r = 32 * qh + i * 4 + j;
                    float w0 = sw0pos[r], w1 = sw0pos[128 + r], w2 = sw0pos[256 + r];
                    float fa = fmaxf(aa[j] + pa0 * w0 + pa1 * w1 + pa2 * w2 + sB0[r], 0.0f);
                    float fb = fmaxf(bb[j] + pb0 * w0 + pb1 * w1 + pb2 * w2 + sB0[r], 0.0f);
                    X32[r * (LD1 / 2) + c2] = packh2(fa, fb);
                }
            }
        }
        CP_WAIT(0);
        __syncthreads();

        // layer 1
        zero_c(c);
        gemm_ms(xu, wu1, mw, nw, lid, c);
        uint32_t pk[2][8][2];
#pragma unroll
        for (int mi = 0; mi < 2; mi++) {
            int r0 = mw * 32 + mi * 16 + (lid >> 2), r1 = r0 + 8;
            float b0 = sB1[r0], b1 = sB1[r1];
#pragma unroll
            for (int nt = 0; nt < 8; nt++) {
                pk[mi][nt][0] = packh2(fmaxf(c[mi][nt][0] + b0, 0.0f),
                                       fmaxf(c[mi][nt][1] + b0, 0.0f));
                pk[mi][nt][1] = packh2(fmaxf(c[mi][nt][2] + b1, 0.0f),
                                       fmaxf(c[mi][nt][3] + b1, 0.0f));
            }
        }
        __syncthreads();
        {
            uint32_t* X32 = (uint32_t*)(smp + X1OFF);
#pragma unroll
            for (int mi = 0; mi < 2; mi++) {
                int r0 = mw * 32 + mi * 16 + (lid >> 2), r1 = r0 + 8;
#pragma unroll
                for (int nt = 0; nt < 8; nt++) {
                    int col = nw * 64 + nt * 8 + (lid & 3) * 2;
                    X32[(r0 * LD1 + col) >> 1] = pk[mi][nt][0];
                    X32[(r1 * LD1 + col) >> 1] = pk[mi][nt][1];
                }
            }
        }
        __syncthreads();

        // layer 2
#pragma unroll 1
        for (int h = 0; h < 2; h++) {
            zero_c(c);
            gemm_ms(xu, h ? wu3 : wu2, mw, nw, lid, c);
#pragma unroll
            for (int mi = 0; mi < 2; mi++) {
                int r0 = mw * 32 + mi * 16 + (lid >> 2);
                int o0 = h * 128 + r0, o1 = o0 + 8;
#pragma unroll
                for (int nt = 0; nt < 8; nt++) {
                    int p = nw * 8 + nt;
                    float m0 = fmaxf(c[mi][nt][0], c[mi][nt][1]);
                    float m1 = fmaxf(c[mi][nt][2], c[mi][nt][3]);
                    m0 = fmaxf(m0, __shfl_xor_sync(0xffffffffu, m0, 1));
                    m0 = fmaxf(m0, __shfl_xor_sync(0xffffffffu, m0, 2));
                    m1 = fmaxf(m1, __shfl_xor_sync(0xffffffffu, m1, 1));
                    m1 = fmaxf(m1, __shfl_xor_sync(0xffffffffu, m1, 2));
                    if ((lid & 3) == 0) {
                        stage[o0 * 16 + p] = f2h(fmaxf(m0 + __ldg(&B2[o0]), 0.0f));
                        stage[o1 * 16 + p] = f2h(fmaxf(m1 + __ldg(&B2[o1]), 0.0f));
                    }
                }
            }
        }
        __syncthreads();
        {
            const uint4* s = (const uint4*)(stage + t * 16);
            uint4* d = (uint4*)(&g_midh[((size_t)b * H2 + t) * NN + n0]);
            d[0] = s[0]; d[1] = s[1];
        }
    }
}

// ---------------------------------------------------------------------------
// mlp2: K-chunk 64, 2-stage ping-pong, 2 CTAs/SM; f1 converted inline (fp32).
// ---------------------------------------------------------------------------
#define M2X0 0
#define M2X1 17408
#define M2W0 34816
#define M2W1 53248
#define M2BIAS 71680
#define DSMEM2 72192

__device__ __forceinline__ void mlp2_issue(int ch, char* smp, int buf,
                                           uint32_t xdst, uint32_t wdst,
                                           const float* __restrict__ f1,
                                           int b, int m0b, int n0, int t) {
    int kg = ch * 64;
    if (kg < 256) {
        const char* xsrc = (const char*)(g_midh + ((size_t)b * H2 + kg) * NN + n0);
#pragma unroll
        for (int k = 0; k < 4; k++) {
            int i = t + k * 256, row = i >> 4, q = i & 15;
            CP16(xdst + (uint32_t)((row * 17 + q) * 16), xsrc + (size_t)row * (NN * 2) + q * 16);
        }
    } else {
        const float* srcf = f1 + ((size_t)b * F1C + (kg - 256)) * NN + n0;
        uint4* d = (uint4*)(smp + (buf ? M2X1 : M2X0));
#pragma unroll
        for (int k = 0; k < 4; k++) {
            int i = t + k * 256, row = i >> 4, q = i & 15;
            const float4* s4 = (const float4*)(srcf + (size_t)row * NN);
            float4 a = s4[q * 2], c2 = s4[q * 2 + 1];
            uint4 v;
            v.x = packh2(a.x, a.y);   v.y = packh2(a.z, a.w);
            v.z = packh2(c2.x, c2.y); v.w = packh2(c2.z, c2.w);
            d[row * 17 + q] = v;
        }
    }
    const char* wsrc = (const char*)(g_w20h + (size_t)m0b * 512 + kg);
#pragma unroll
    for (int k = 0; k < 4; k++) {
        int i = t + k * 256, row = i >> 3, q = i & 7;
        CP16(wdst + (uint32_t)((row * 9 + q) * 16), wsrc + (size_t)row * 1024 + q * 16);
    }
}

__global__ __launch_bounds__(256, 2) void mlp2_mma(
    const float* __restrict__ f1,
    const float* __restrict__ Bi, float* __restrict__ out) {
    extern __shared__ __align__(32) char smp[];
    const int t = threadIdx.x, wid = t >> 5, lid = t & 31;
    const int mw = wid & 3, nw = wid >> 2;
    const int b = blockIdx.z, m0b = blockIdx.y * 128, n0 = blockIdx.x * 128;

    const uint32_t xu0 = smem_u32(smp + M2X0), xu1 = smem_u32(smp + M2X1);
    const uint32_t wu0 = smem_u32(smp + M2W0), wu1 = smem_u32(smp + M2W1);
    float* sBias = (float*)(smp + M2BIAS);

    if (t < 128) sBias[t] = Bi[m0b + t];

    mlp2_issue(0, smp, 0, xu0, wu0, f1, b, m0b, n0, t); CP_COMMIT();
    mlp2_issue(1, smp, 1, xu1, wu1, f1, b, m0b, n0, t); CP_COMMIT();

    float c[2][8][4];
    zero_c(c);

#pragma unroll 1
    for (int ch = 0; ch < 8; ch++) {
        CP_WAIT(1);
        __syncthreads();
        if (ch & 1) gemm_k64(xu1, wu1, mw, nw, lid, c);
        else        gemm_k64(xu0, wu0, mw, nw, lid, c);
        __syncthreads();
        if (ch + 2 < 8)
            mlp2_issue(ch + 2, smp, ch & 1, (ch & 1) ? xu1 : xu0, (ch & 1) ? wu1 : wu0,
                       f1, b, m0b, n0, t);
        CP_COMMIT();
    }

#pragma unroll
    for (int mi = 0; mi < 2; mi++) {
        int r0 = mw * 32 + mi * 16 + (lid >> 2), r1 = r0 + 8;
        float b0 = sBias[r0], b1 = sBias[r1];
#pragma unroll
        for (int nt = 0; nt < 8; nt++) {
            int col = n0 + nw * 64 + nt * 8 + (lid & 3) * 2;
            float2 v0 = make_float2(fmaxf(c[mi][nt][0] + b0, 0.0f),
                                    fmaxf(c[mi][nt][1] + b0, 0.0f));
            float2 v1 = make_float2(fmaxf(c[mi][nt][2] + b1, 0.0f),
                                    fmaxf(c[mi][nt][3] + b1, 0.0f));
            *(float2*)(out + ((size_t)b * H2 + m0b + r0) * NN + col) = v0;
            *(float2*)(out + ((size_t)b * H2 + m0b + r1) * NN + col) = v1;
        }
    }
}

// ---------------------------------------------------------------------------
extern "C" void kernel_launch(void* const* d_in, const int* in_sizes, int n_in,
                              void* d_out, int out_size) {
    const float* pos1     = (const float*)d_in[0];
    const float* pos2     = (const float*)d_in[1];
    const float* feature1 = (const float*)d_in[2];
    const float* feature2 = (const float*)d_in[3];
    const float* w1_0 = (const float*)d_in[4];
    const float* s1_0 = (const float*)d_in[5];
    const float* b1_0 = (const float*)d_in[6];
    const float* w1_1 = (const float*)d_in[7];
    const float* s1_1 = (const float*)d_in[8];
    const float* b1_1 = (const float*)d_in[9];
    const float* w1_2 = (const float*)d_in[10];
    const float* s1_2 = (const float*)d_in[11];
    const float* b1_2 = (const float*)d_in[12];
    const float* w2_0 = (const float*)d_in[13];
    const float* s2_0 = (const float*)d_in[14];
    const float* b2_0 = (const float*)d_in[15];
    float* out = (float*)d_out;

    static int nsm = 0;
    static int init_done = 0;
    if (!init_done) {
        cudaFuncSetAttribute(mlp1_mma, cudaFuncAttributeMaxDynamicSharedMemorySize, DSMEM1);
        cudaFuncSetAttribute(mlp2_mma, cudaFuncAttributeMaxDynamicSharedMemorySize, DSMEM2);
        cudaDeviceGetAttribute(&nsm, cudaDevAttrMultiProcessorCount, 0);
        init_done = 1;
    }

    pre_kernel<<<PRE_BLKS, 256, PRE_SMEM>>>(pos1, pos2, feature2,
                                            w1_0, s1_0, w1_1, s1_1,
                                            w1_2, s1_2, w2_0, s2_0);
    mlp1_mma<<<nsm, 256, DSMEM1>>>(pos1, pos2, w1_0, s1_0, b1_0, b1_1, b1_2);
    mlp2_mma<<<dim3(NN / 128, 2, BB), 256, DSMEM2>>>(feature1, b2_0, out);
}

// round 17
// speedup vs baseline: 1.6299x; 1.6299x over previous
#include <cuda_runtime.h>
#include <cuda_fp16.h>
#include <cstdint>

#define BB 4
#define NN 8192
#define MM 2048
#define KK 8
#define F1C 256
#define F2C 256
#define C0 259
#define H2 256
#define C2IN 512
#define NTILES 2048

// ---------------- scratch (__device__ globals) ----------------
__device__ float g_y0[(size_t)BB * MM * 128];                      // s0 * (W0_feat @ feature2)
__device__ __half g_midh[(size_t)BB * H2 * NN];                    // mlp1 output (fp16)
__device__ int   g_idx[BB * NN * KK];
__device__ __align__(16) uint16_t g_w1h[128 * 128];
__device__ __align__(16) uint16_t g_w2h[256 * 128];
__device__ __align__(16) uint16_t g_w20h[256 * 512];

__device__ __forceinline__ uint16_t f2h(float x) {
    return __half_as_ushort(__float2half_rn(x));
}
__device__ __forceinline__ uint32_t smem_u32(const void* p) {
    uint32_t a;
    asm("{ .reg .u64 t; cvta.to.shared.u64 t, %1; cvt.u32.u64 %0, t; }" : "=r"(a) : "l"(p));
    return a;
}
__device__ __forceinline__ uint32_t packh2(float lo, float hi) {
    return (uint32_t)f2h(lo) | ((uint32_t)f2h(hi) << 16);
}

// ---------------- mma.sync / ldmatrix / cp.async primitives ----------------
__device__ __forceinline__ void ldsm4(uint32_t r[4], uint32_t addr) {
    asm volatile("ldmatrix.sync.aligned.m8n8.x4.shared.b16 {%0,%1,%2,%3}, [%4];"
                 : "=r"(r[0]), "=r"(r[1]), "=r"(r[2]), "=r"(r[3]) : "r"(addr));
}
__device__ __forceinline__ void ldsm4t(uint32_t r[4], uint32_t addr) {
    asm volatile("ldmatrix.sync.aligned.m8n8.x4.trans.shared.b16 {%0,%1,%2,%3}, [%4];"
                 : "=r"(r[0]), "=r"(r[1]), "=r"(r[2]), "=r"(r[3]) : "r"(addr));
}
__device__ __forceinline__ void mma16816(float c[4], const uint32_t a[4], const uint32_t* b) {
    asm volatile("mma.sync.aligned.m16n8k16.row.col.f32.f16.f16.f32 "
                 "{%0,%1,%2,%3}, {%4,%5,%6,%7}, {%8,%9}, {%0,%1,%2,%3};"
                 : "+f"(c[0]), "+f"(c[1]), "+f"(c[2]), "+f"(c[3])
                 : "r"(a[0]), "r"(a[1]), "r"(a[2]), "r"(a[3]), "r"(b[0]), "r"(b[1]));
}
#define CP16(dst, src) asm volatile("cp.async.cg.shared.global [%0], [%1], 16;" :: "r"(dst), "l"(src))
#define CP_COMMIT()    asm volatile("cp.async.commit_group;")
#define CP_WAIT(n)     asm volatile("cp.async.wait_group %0;" :: "n"(n))

#define LD1 136
#define LDW 72

__device__ __forceinline__ void zero_c(float c[2][8][4]) {
#pragma unroll
    for (int mi = 0; mi < 2; mi++)
#pragma unroll
        for (int nt = 0; nt < 8; nt++)
#pragma unroll
            for (int q = 0; q < 4; q++) c[mi][nt][q] = 0.0f;
}

// K=128 GEMM (W stride LD1): rows [mw*32,+32) x cols [nw*64,+64)
__device__ __forceinline__ void gemm_ms(uint32_t xu, uint32_t wu, int mw, int nw,
                                        int lid, float c[2][8][4]) {
    uint32_t aA0 = wu + (uint32_t)(((mw * 32 + (lid & 15)) * LD1 + (lid >> 4) * 8) * 2);
    uint32_t aA1 = aA0 + 16 * LD1 * 2;
    uint32_t aB  = xu + (uint32_t)(((lid & 15) * LD1 + nw * 64 + (lid >> 4) * 8) * 2);
#pragma unroll
    for (int kt = 0; kt < 8; kt++) {
        uint32_t A0[4], A1[4];
        ldsm4(A0, aA0 + kt * 32);
        ldsm4(A1, aA1 + kt * 32);
#pragma unroll
        for (int ng = 0; ng < 4; ng++) {
            uint32_t Bv[4];
            ldsm4t(Bv, aB + kt * 16 * LD1 * 2 + ng * 32);
            mma16816(c[0][2 * ng],     A0, Bv);
            mma16816(c[0][2 * ng + 1], A0, Bv + 2);
            mma16816(c[1][2 * ng],     A1, Bv);
            mma16816(c[1][2 * ng + 1], A1, Bv + 2);
        }
    }
}

// K=64 GEMM (W stride LDW=72)
__device__ __forceinline__ void gemm_k64(uint32_t xu, uint32_t wu, int mw, int nw,
                                         int lid, float c[2][8][4]) {
    uint32_t aA0 = wu + (uint32_t)(((mw * 32 + (lid & 15)) * LDW + (lid >> 4) * 8) * 2);
    uint32_t aA1 = aA0 + 16 * LDW * 2;
    uint32_t aB  = xu + (uint32_t)(((lid & 15) * LD1 + nw * 64 + (lid >> 4) * 8) * 2);
#pragma unroll
    for (int kt = 0; kt < 4; kt++) {
        uint32_t A0[4], A1[4];
        ldsm4(A0, aA0 + kt * 32);
        ldsm4(A1, aA1 + kt * 32);
#pragma unroll
        for (int ng = 0; ng < 4; ng++) {
            uint32_t Bv[4];
            ldsm4t(Bv, aB + kt * 16 * LD1 * 2 + ng * 32);
            mma16816(c[0][2 * ng],     A0, Bv);
            mma16816(c[0][2 * ng + 1], A0, Bv + 2);
            mma16816(c[1][2 * ng],     A1, Bv);
            mma16816(c[1][2 * ng + 1], A1, Bv + 2);
        }
    }
}

// cp.async a 128x128 fp16 matrix (row stride srcstride bytes) into LD1-padded smem
__device__ __forceinline__ void cpa_mat(uint32_t dst, const char* src, size_t srcstride, int t) {
#pragma unroll
    for (int k = 0; k < 8; k++) {
        int i = t + k * 256, row = i >> 4, q = i & 15;
        CP16(dst + (uint32_t)(((row * 17) + q) * 16), src + (size_t)row * srcstride + q * 16);
    }
}

// ---------------------------------------------------------------------------
// prep: weights -> fp16 with BN scale folded in (weights ONLY)
// ---------------------------------------------------------------------------
__global__ void prep_kernel(const float* __restrict__ W1, const float* __restrict__ S1,
                            const float* __restrict__ W2, const float* __restrict__ S2,
                            const float* __restrict__ W20, const float* __restrict__ S20) {
    int t = blockIdx.x * blockDim.x + threadIdx.x;
    if (t < 16384) {
        g_w1h[t] = f2h(W1[t] * __ldg(&S1[t >> 7]));
    } else if (t < 49152) {
        int i = t - 16384;
        g_w2h[i] = f2h(W2[i] * __ldg(&S2[i >> 7]));
    } else if (t < 180224) {
        int i = t - 49152;
        g_w20h[i] = f2h(W20[i] * __ldg(&S20[i >> 9]));
    }
}

// ---------------------------------------------------------------------------
// y0: g_y0[b][m][r] = S0[r] * sum_c W0[r][c] * feature2[b][c][m]   (fp32)
// ---------------------------------------------------------------------------
__global__ __launch_bounds__(256) void y0_kernel(const float* __restrict__ W0,
                                                 const float* __restrict__ S0,
                                                 const float* __restrict__ f2) {
    __shared__ float tile[256][33];
    const int b = blockIdx.y, m0 = blockIdx.x * 32, t = threadIdx.x;
    for (int i = t; i < 256 * 32; i += 256) {
        int c = i >> 5, j = i & 31;
        tile[c][j] = f2[((size_t)b * F2C + c) * MM + m0 + j];
    }
    __syncthreads();
    const int r = t & 127, mh = t >> 7;
    float acc[16];
#pragma unroll
    for (int j = 0; j < 16; j++) acc[j] = 0.0f;
    const float* wrow = W0 + (size_t)r * C0;
#pragma unroll 4
    for (int c = 0; c < 256; c++) {
        float w = __ldg(&wrow[c]);
#pragma unroll
        for (int j = 0; j < 16; j++) acc[j] = fmaf(w, tile[c][mh * 16 + j], acc[j]);
    }
    float s0 = __ldg(&S0[r]);
    for (int j = 0; j < 16; j++)
        g_y0[((size_t)b * MM + m0 + mh * 16 + j) * 128 + r] = acc[j] * s0;
}

// ---------------------------------------------------------------------------
// KNN: full scan, packed f32x2 FMA, SORTED top-8 (descending; branchless
// compare-swap bubble insert; ties keep earliest index). 128-thr blocks.
// ---------------------------------------------------------------------------
__global__ __launch_bounds__(128) void knn_scan(const float* __restrict__ pos1,
                                                const float* __restrict__ pos2) {
    __shared__ __align__(16) float sXY[MM * 2];
    __shared__ __align__(16) float sZW[MM * 2];
    const int b = blockIdx.y;
    const float* p2 = pos2 + (size_t)b * 3 * MM;
    for (int m = threadIdx.x; m < MM; m += 128) {
        float x = p2[m], y = p2[MM + m], z = p2[2 * MM + m];
        int pp = m >> 1, ln = m & 1;
        sXY[pp * 4 + ln] = x;     sXY[pp * 4 + 2 + ln] = y;
        sZW[pp * 4 + ln] = z;     sZW[pp * 4 + 2 + ln] = x * x + y * y + z * z;
    }
    __syncthreads();

    const int n = blockIdx.x * 128 + threadIdx.x;
    const float* p1 = pos1 + (size_t)b * 3 * NN;
    const float px = p1[n], py = p1[NN + n], pz = p1[2 * NN + n];
    const float n1 = px * px + py * py + pz * pz;
    const float mx2 = -2.0f * px, my2 = -2.0f * py, mz2 = -2.0f * pz;
    uint64_t QX, QY, QZ, NP;
    asm("mov.b64 %0, {%1, %2};" : "=l"(QX) : "f"(mx2), "f"(mx2));
    asm("mov.b64 %0, {%1, %2};" : "=l"(QY) : "f"(my2), "f"(my2));
    asm("mov.b64 %0, {%1, %2};" : "=l"(QZ) : "f"(mz2), "f"(mz2));
    asm("mov.b64 %0, {%1, %2};" : "=l"(NP) : "f"(n1), "f"(n1));

    // sorted descending: bestd[0] = current worst (max) of the kept 8
    float bestd[KK]; int besti[KK];
#pragma unroll
    for (int i = 0; i < KK; i++) { bestd[i] = 1e30f; besti[i] = 0; }

    auto ins = [&](float dv, int iv) {
        if (dv < bestd[0]) {
            bestd[0] = dv; besti[0] = iv;
#pragma unroll
            for (int i = 0; i < KK - 1; i++) {
                bool sw = bestd[i] < bestd[i + 1];        // strict: equal stays shallower
                float td = sw ? bestd[i + 1] : bestd[i];
                float bd = sw ? bestd[i]     : bestd[i + 1];
                int   ti = sw ? besti[i + 1] : besti[i];
                int   bi = sw ? besti[i]     : besti[i + 1];
                bestd[i] = td;     besti[i] = ti;
                bestd[i + 1] = bd; besti[i + 1] = bi;
            }
        }
    };

    uint32_t aXY = smem_u32(sXY), aZW = smem_u32(sZW);
    for (int g = 0; g < MM / 4; g++) {
        uint64_t X0, Y0, X1, Y1, Z0, W0v, Z1, W1v, t0, t1;
        asm("ld.shared.v2.u64 {%0,%1}, [%2];"    : "=l"(X0), "=l"(Y0) : "r"(aXY));
        asm("ld.shared.v2.u64 {%0,%1}, [%2+16];" : "=l"(X1), "=l"(Y1) : "r"(aXY));
        asm("ld.shared.v2.u64 {%0,%1}, [%2];"    : "=l"(Z0), "=l"(W0v) : "r"(aZW));
        asm("ld.shared.v2.u64 {%0,%1}, [%2+16];" : "=l"(Z1), "=l"(W1v) : "r"(aZW));
        aXY += 32; aZW += 32;
        asm("add.rn.f32x2 %0, %1, %2;"     : "=l"(t0) : "l"(W0v), "l"(NP));
        asm("fma.rn.f32x2 %0, %1, %2, %3;" : "=l"(t0) : "l"(QZ), "l"(Z0), "l"(t0));
        asm("fma.rn.f32x2 %0, %1, %2, %3;" : "=l"(t0) : "l"(QY), "l"(Y0), "l"(t0));
        asm("fma.rn.f32x2 %0, %1, %2, %3;" : "=l"(t0) : "l"(QX), "l"(X0), "l"(t0));
        asm("add.rn.f32x2 %0, %1, %2;"     : "=l"(t1) : "l"(W1v), "l"(NP));
        asm("fma.rn.f32x2 %0, %1, %2, %3;" : "=l"(t1) : "l"(QZ), "l"(Z1), "l"(t1));
        asm("fma.rn.f32x2 %0, %1, %2, %3;" : "=l"(t1) : "l"(QY), "l"(Y1), "l"(t1));
        asm("fma.rn.f32x2 %0, %1, %2, %3;" : "=l"(t1) : "l"(QX), "l"(X1), "l"(t1));
        float d0, d1, d2, d3;
        asm("mov.b64 {%0,%1}, %2;" : "=f"(d0), "=f"(d1) : "l"(t0));
        asm("mov.b64 {%0,%1}, %2;" : "=f"(d2), "=f"(d3) : "l"(t1));
        float mn = fminf(fminf(d0, d1), fminf(d2, d3));
        if (mn < bestd[0]) {
            int ib = g * 4;
            ins(d0, ib); ins(d1, ib + 1); ins(d2, ib + 2); ins(d3, ib + 3);
        }
    }
    int* out = g_idx + ((size_t)b * NN + n) * KK;
#pragma unroll
    for (int i = 0; i < KK; i++) out[i] = besti[i];   // order irrelevant (maxpool)
}

// ---------------------------------------------------------------------------
// mlp1 PERSISTENT: all weights resident; tiles of 16 points.
// ---------------------------------------------------------------------------
#define X1OFF 0
#define WS1 34816
#define WS2 69632
#define WS3 104448
#define STGOFF 139264
#define PRMOFF 147456
#define DSMEM1 150528

__global__ __launch_bounds__(256, 1) void mlp1_mma(
    const float* __restrict__ pos1, const float* __restrict__ pos2,
    const float* __restrict__ W0full, const float* __restrict__ S0,
    const float* __restrict__ B0, const float* __restrict__ B1,
    const float* __restrict__ B2) {
    extern __shared__ __align__(32) char smp[];

    const int t = threadIdx.x, wid = t >> 5, lid = t & 31;
    const int mw = wid & 3, nw = wid >> 2;

    const uint32_t xu  = smem_u32(smp + X1OFF);
    const uint32_t wu1 = smem_u32(smp + WS1);
    const uint32_t wu2 = smem_u32(smp + WS2);
    const uint32_t wu3 = smem_u32(smp + WS3);
    uint16_t* stage  = (uint16_t*)(smp + STGOFF);
    int*   sidx   = (int*)(smp + PRMOFF);
    float* sw0pos = (float*)(smp + PRMOFF + 512);
    float* sB0    = (float*)(smp + PRMOFF + 2048);
    float* sB1    = (float*)(smp + PRMOFF + 2560);

    cpa_mat(wu1, (const char*)g_w1h, 256, t);
    cpa_mat(wu2, (const char*)g_w2h, 256, t);
    cpa_mat(wu3, (const char*)(g_w2h + 16384), 256, t);
    CP_COMMIT();

    for (int i = t; i < 384; i += 256) {
        int d = i >> 7, r = i & 127;
        sw0pos[i] = W0full[(size_t)r * C0 + 256 + d] * __ldg(&S0[r]);
    }
    if (t < 128) { sB0[t] = B0[t]; sB1[t] = B1[t]; }

    float c[2][8][4];

    for (int tile = blockIdx.x; tile < NTILES; tile += gridDim.x) {
        const int b = tile >> 9, n0 = (tile & 511) * 16;

        if (t < 128) sidx[t] = g_idx[((size_t)b * NN + n0) * KK + t];
        __syncthreads();

        // epilogue 0: gather y0 + pos correction, +b, ReLU -> X0 [k][n]
        {
            int c2 = t & 63, qh = t >> 6;
            int ca = 2 * c2;
            int ma = sidx[ca], mb2 = sidx[ca + 1];
            int n = n0 + (c2 >> 2);
            float pa0 = pos2[((size_t)b * 3 + 0) * MM + ma]  - pos1[((size_t)b * 3 + 0) * NN + n];
            float pa1 = pos2[((size_t)b * 3 + 1) * MM + ma]  - pos1[((size_t)b * 3 + 1) * NN + n];
            float pa2 = pos2[((size_t)b * 3 + 2) * MM + ma]  - pos1[((size_t)b * 3 + 2) * NN + n];
            float pb0 = pos2[((size_t)b * 3 + 0) * MM + mb2] - pos1[((size_t)b * 3 + 0) * NN + n];
            float pb1 = pos2[((size_t)b * 3 + 1) * MM + mb2] - pos1[((size_t)b * 3 + 1) * NN + n];
            float pb2 = pos2[((size_t)b * 3 + 2) * MM + mb2] - pos1[((size_t)b * 3 + 2) * NN + n];
            const float4* ya = (const float4*)(g_y0 + ((size_t)b * MM + ma)  * 128 + 32 * qh);
            const float4* yb = (const float4*)(g_y0 + ((size_t)b * MM + mb2) * 128 + 32 * qh);
            uint32_t* X32 = (uint32_t*)(smp + X1OFF);
#pragma unroll
            for (int i = 0; i < 8; i++) {
                float4 va = ya[i], vb = yb[i];
                float aa[4] = {va.x, va.y, va.z, va.w};
                float bb[4] = {vb.x, vb.y, vb.z, vb.w};
#pragma unroll
                for (int j = 0; j < 4; j++) {
                    int r = 32 * qh + i * 4 + j;
                    float w0 = sw0pos[r], w1 = sw0pos[128 + r], w2 = sw0pos[256 + r];
                    float fa = fmaxf(aa[j] + pa0 * w0 + pa1 * w1 + pa2 * w2 + sB0[r], 0.0f);
                    float fb = fmaxf(bb[j] + pb0 * w0 + pb1 * w1 + pb2 * w2 + sB0[r], 0.0f);
                    X32[r * (LD1 / 2) + c2] = packh2(fa, fb);
                }
            }
        }
        CP_WAIT(0);
        __syncthreads();

        // layer 1
        zero_c(c);
        gemm_ms(xu, wu1, mw, nw, lid, c);
        uint32_t pk[2][8][2];
#pragma unroll
        for (int mi = 0; mi < 2; mi++) {
            int r0 = mw * 32 + mi * 16 + (lid >> 2), r1 = r0 + 8;
            float b0 = sB1[r0], b1 = sB1[r1];
#pragma unroll
            for (int nt = 0; nt < 8; nt++) {
                pk[mi][nt][0] = packh2(fmaxf(c[mi][nt][0] + b0, 0.0f),
                                       fmaxf(c[mi][nt][1] + b0, 0.0f));
                pk[mi][nt][1] = packh2(fmaxf(c[mi][nt][2] + b1, 0.0f),
                                       fmaxf(c[mi][nt][3] + b1, 0.0f));
            }
        }
        __syncthreads();
        {
            uint32_t* X32 = (uint32_t*)(smp + X1OFF);
#pragma unroll
            for (int mi = 0; mi < 2; mi++) {
                int r0 = mw * 32 + mi * 16 + (lid >> 2), r1 = r0 + 8;
#pragma unroll
                for (int nt = 0; nt < 8; nt++) {
                    int col = nw * 64 + nt * 8 + (lid & 3) * 2;
                    X32[(r0 * LD1 + col) >> 1] = pk[mi][nt][0];
                    X32[(r1 * LD1 + col) >> 1] = pk[mi][nt][1];
                }
            }
        }
        __syncthreads();

        // layer 2
#pragma unroll 1
        for (int h = 0; h < 2; h++) {
            zero_c(c);
            gemm_ms(xu, h ? wu3 : wu2, mw, nw, lid, c);
#pragma unroll
            for (int mi = 0; mi < 2; mi++) {
                int r0 = mw * 32 + mi * 16 + (lid >> 2);
                int o0 = h * 128 + r0, o1 = o0 + 8;
#pragma unroll
                for (int nt = 0; nt < 8; nt++) {
                    int p = nw * 8 + nt;
                    float m0 = fmaxf(c[mi][nt][0], c[mi][nt][1]);
                    float m1 = fmaxf(c[mi][nt][2], c[mi][nt][3]);
                    m0 = fmaxf(m0, __shfl_xor_sync(0xffffffffu, m0, 1));
                    m0 = fmaxf(m0, __shfl_xor_sync(0xffffffffu, m0, 2));
                    m1 = fmaxf(m1, __shfl_xor_sync(0xffffffffu, m1, 1));
                    m1 = fmaxf(m1, __shfl_xor_sync(0xffffffffu, m1, 2));
                    if ((lid & 3) == 0) {
                        stage[o0 * 16 + p] = f2h(fmaxf(m0 + __ldg(&B2[o0]), 0.0f));
                        stage[o1 * 16 + p] = f2h(fmaxf(m1 + __ldg(&B2[o1]), 0.0f));
                    }
                }
            }
        }
        __syncthreads();
        {
            const uint4* s = (const uint4*)(stage + t * 16);
            uint4* d = (uint4*)(&g_midh[((size_t)b * H2 + t) * NN + n0]);
            d[0] = s[0]; d[1] = s[1];
        }
    }
}

// ---------------------------------------------------------------------------
// mlp2: K-chunk 64, 2-stage ping-pong, 2 CTAs/SM; f1 converted inline (fp32).
// ---------------------------------------------------------------------------
#define M2X0 0
#define M2X1 17408
#define M2W0 34816
#define M2W1 53248
#define M2BIAS 71680
#define DSMEM2 72192

__device__ __forceinline__ void mlp2_issue(int ch, char* smp, int buf,
                                           uint32_t xdst, uint32_t wdst,
                                           const float* __restrict__ f1,
                                           int b, int m0b, int n0, int t) {
    int kg = ch * 64;
    if (kg < 256) {
        const char* xsrc = (const char*)(g_midh + ((size_t)b * H2 + kg) * NN + n0);
#pragma unroll
        for (int k = 0; k < 4; k++) {
            int i = t + k * 256, row = i >> 4, q = i & 15;
            CP16(xdst + (uint32_t)((row * 17 + q) * 16), xsrc + (size_t)row * (NN * 2) + q * 16);
        }
    } else {
        const float* srcf = f1 + ((size_t)b * F1C + (kg - 256)) * NN + n0;
        uint4* d = (uint4*)(smp + (buf ? M2X1 : M2X0));
#pragma unroll
        for (int k = 0; k < 4; k++) {
            int i = t + k * 256, row = i >> 4, q = i & 15;
            const float4* s4 = (const float4*)(srcf + (size_t)row * NN);
            float4 a = s4[q * 2], c2 = s4[q * 2 + 1];
            uint4 v;
            v.x = packh2(a.x, a.y);   v.y = packh2(a.z, a.w);
            v.z = packh2(c2.x, c2.y); v.w = packh2(c2.z, c2.w);
            d[row * 17 + q] = v;
        }
    }
    const char* wsrc = (const char*)(g_w20h + (size_t)m0b * 512 + kg);
#pragma unroll
    for (int k = 0; k < 4; k++) {
        int i = t + k * 256, row = i >> 3, q = i & 7;
        CP16(wdst + (uint32_t)((row * 9 + q) * 16), wsrc + (size_t)row * 1024 + q * 16);
    }
}

__global__ __launch_bounds__(256, 2) void mlp2_mma(
    const float* __restrict__ f1,
    const float* __restrict__ Bi, float* __restrict__ out) {
    extern __shared__ __align__(32) char smp[];
    const int t = threadIdx.x, wid = t >> 5, lid = t & 31;
    const int mw = wid & 3, nw = wid >> 2;
    const int b = blockIdx.z, m0b = blockIdx.y * 128, n0 = blockIdx.x * 128;

    const uint32_t xu0 = smem_u32(smp + M2X0), xu1 = smem_u32(smp + M2X1);
    const uint32_t wu0 = smem_u32(smp + M2W0), wu1 = smem_u32(smp + M2W1);
    float* sBias = (float*)(smp + M2BIAS);

    if (t < 128) sBias[t] = Bi[m0b + t];

    mlp2_issue(0, smp, 0, xu0, wu0, f1, b, m0b, n0, t); CP_COMMIT();
    mlp2_issue(1, smp, 1, xu1, wu1, f1, b, m0b, n0, t); CP_COMMIT();

    float c[2][8][4];
    zero_c(c);

#pragma unroll 1
    for (int ch = 0; ch < 8; ch++) {
        CP_WAIT(1);
        __syncthreads();
        if (ch & 1) gemm_k64(xu1, wu1, mw, nw, lid, c);
        else        gemm_k64(xu0, wu0, mw, nw, lid, c);
        __syncthreads();
        if (ch + 2 < 8)
            mlp2_issue(ch + 2, smp, ch & 1, (ch & 1) ? xu1 : xu0, (ch & 1) ? wu1 : wu0,
                       f1, b, m0b, n0, t);
        CP_COMMIT();
    }

#pragma unroll
    for (int mi = 0; mi < 2; mi++) {
        int r0 = mw * 32 + mi * 16 + (lid >> 2), r1 = r0 + 8;
        float b0 = sBias[r0], b1 = sBias[r1];
#pragma unroll
        for (int nt = 0; nt < 8; nt++) {
            int col = n0 + nw * 64 + nt * 8 + (lid & 3) * 2;
            float2 v0 = make_float2(fmaxf(c[mi][nt][0] + b0, 0.0f),
                                    fmaxf(c[mi][nt][1] + b0, 0.0f));
            float2 v1 = make_float2(fmaxf(c[mi][nt][2] + b1, 0.0f),
                                    fmaxf(c[mi][nt][3] + b1, 0.0f));
            *(float2*)(out + ((size_t)b * H2 + m0b + r0) * NN + col) = v0;
            *(float2*)(out + ((size_t)b * H2 + m0b + r1) * NN + col) = v1;
        }
    }
}

// ---------------------------------------------------------------------------
extern "C" void kernel_launch(void* const* d_in, const int* in_sizes, int n_in,
                              void* d_out, int out_size) {
    const float* pos1     = (const float*)d_in[0];
    const float* pos2     = (const float*)d_in[1];
    const float* feature1 = (const float*)d_in[2];
    const float* feature2 = (const float*)d_in[3];
    const float* w1_0 = (const float*)d_in[4];
    const float* s1_0 = (const float*)d_in[5];
    const float* b1_0 = (const float*)d_in[6];
    const float* w1_1 = (const float*)d_in[7];
    const float* s1_1 = (const float*)d_in[8];
    const float* b1_1 = (const float*)d_in[9];
    const float* w1_2 = (const float*)d_in[10];
    const float* s1_2 = (const float*)d_in[11];
    const float* b1_2 = (const float*)d_in[12];
    const float* w2_0 = (const float*)d_in[13];
    const float* s2_0 = (const float*)d_in[14];
    const float* b2_0 = (const float*)d_in[15];
    float* out = (float*)d_out;

    static int nsm = 0;
    static cudaStream_t s2;
    static cudaEvent_t ev0, ev1;
    static int init_done = 0;
    if (!init_done) {
        cudaFuncSetAttribute(mlp1_mma, cudaFuncAttributeMaxDynamicSharedMemorySize, DSMEM1);
        cudaFuncSetAttribute(mlp2_mma, cudaFuncAttributeMaxDynamicSharedMemorySize, DSMEM2);
        cudaDeviceGetAttribute(&nsm, cudaDevAttrMultiProcessorCount, 0);
        cudaStreamCreateWithFlags(&s2, cudaStreamNonBlocking);
        cudaEventCreateWithFlags(&ev0, cudaEventDisableTiming);
        cudaEventCreateWithFlags(&ev1, cudaEventDisableTiming);
        init_done = 1;
    }

    // fork: prep+y0 on side stream, knn (longer) on main stream
    cudaEventRecord(ev0, 0);
    cudaStreamWaitEvent(s2, ev0, 0);
    prep_kernel<<<704, 256, 0, s2>>>(w1_1, s1_1, w1_2, s1_2, w2_0, s2_0);
    y0_kernel<<<dim3(MM / 32, BB), 256, 0, s2>>>(w1_0, s1_0, feature2);
    cudaEventRecord(ev1, s2);

    knn_scan<<<dim3(NN / 128, BB), 128>>>(pos1, pos2);

    cudaStreamWaitEvent(0, ev1, 0);                   // join

    mlp1_mma<<<nsm, 256, DSMEM1>>>(pos1, pos2, w1_0, s1_0, b1_0, b1_1, b1_2);
    mlp2_mma<<<dim3(NN / 128, 2, BB), 256, DSMEM2>>>(feature1, b2_0, out);
}